// round 2
// baseline (speedup 1.0000x reference)
#include <cuda_runtime.h>

#define F_NODES 16384
#define DEG 8
#define E (F_NODES * DEG)   // 131072
#define B 64
#define H 16
#define LAYERS 10

#define NPB 8               // nodes per block (1 warp per node)
#define NODE_SMEM 280       // floats per node in smem (128 W1 + 128 W2 + 16 b1 + 8 b2)

typedef unsigned long long u64;

// Scratch buffers in (E, B) transposed layout.
__device__ float g_x0T[(size_t)E * B];
__device__ float g_xA [(size_t)E * B];
__device__ float g_xB [(size_t)E * B];

__device__ __forceinline__ u64 pack2(float lo, float hi) {
    u64 r; asm("mov.b64 %0, {%1, %2};" : "=l"(r) : "f"(lo), "f"(hi)); return r;
}
__device__ __forceinline__ void unpack2(u64 v, float& lo, float& hi) {
    asm("mov.b64 {%0, %1}, %2;" : "=f"(lo), "=f"(hi) : "l"(v));
}
__device__ __forceinline__ void fma2(u64& d, u64 a, u64 b, u64 c) {
    asm("fma.rn.f32x2 %0, %1, %2, %3;" : "=l"(d) : "l"(a), "l"(b), "l"(c));
}
__device__ __forceinline__ u64 add2(u64 a, u64 b) {
    u64 r; asm("add.rn.f32x2 %0, %1, %2;" : "=l"(r) : "l"(a), "l"(b)); return r;
}
// Streaming (evict-first) 8-byte global load for dead-after-read data.
__device__ __forceinline__ u64 ldg_cs64(const float* p) {
    u64 r; asm("ld.global.cs.b64 %0, [%1];" : "=l"(r) : "l"(p)); return r;
}
// Branchless ELU (alpha=1): max(x,0) + (exp(min(x,0)) - 1)
__device__ __forceinline__ float elu1(float x) {
    return fmaxf(x, 0.0f) + (__expf(fminf(x, 0.0f)) - 1.0f);
}

// (B, E) row-major -> (E, B)
__global__ void k_transpose_in(const float* __restrict__ in, float* __restrict__ out) {
    __shared__ float t[32][33];
    int e0 = blockIdx.x * 32, b0 = blockIdx.y * 32;
    int tx = threadIdx.x, ty = threadIdx.y;
    t[ty][tx] = in[(size_t)(b0 + ty) * E + e0 + tx];
    __syncthreads();
    out[(size_t)(e0 + ty) * B + b0 + tx] = t[tx][ty];
}

// (E, B) -> (B, E) row-major
__global__ void k_transpose_out(const float* __restrict__ in, float* __restrict__ out) {
    __shared__ float t[32][33];
    int e0 = blockIdx.x * 32, b0 = blockIdx.y * 32;
    int tx = threadIdx.x, ty = threadIdx.y;
    t[ty][tx] = in[(size_t)(e0 + ty) * B + b0 + tx];
    __syncthreads();
    out[(size_t)(b0 + ty) * E + e0 + tx] = t[tx][ty];
}

// One GSNN layer in (E, B) space. One warp per node, 2 batch elems per thread.
__global__ __launch_bounds__(NPB * 32, 4)
void layer_kernel(const float* __restrict__ src, float* __restrict__ dst,
                  const float* __restrict__ W1, const float* __restrict__ b1,
                  const float* __restrict__ W2, const float* __restrict__ b2,
                  const int* __restrict__ in_ixs, const float* __restrict__ x0T) {
    __shared__ float sw[NPB * NODE_SMEM];
    const int lane = threadIdx.x & 31;  // batch pair index: handles b = 2*lane, 2*lane+1
    const int nl   = threadIdx.x >> 5;  // node within block (= warp id)
    const int node = blockIdx.x * NPB + nl;

    // Per-warp weight staging: 32 lanes stage 280 floats of this node.
    {
        const float4* gW1 = (const float4*)(W1 + (size_t)node * 128);
        const float4* gW2 = (const float4*)(W2 + (size_t)node * 128);
        float4* s1 = (float4*)(sw + nl * NODE_SMEM);
        float4* s2 = (float4*)(sw + nl * NODE_SMEM + 128);
        s1[lane] = gW1[lane];
        s2[lane] = gW2[lane];
        if (lane < 16) sw[nl * NODE_SMEM + 256 + lane] = b1[(size_t)node * 16 + lane];
        if (lane >= 16 && lane < 24)
            sw[nl * NODE_SMEM + 272 + (lane - 16)] = b2[(size_t)node * 8 + (lane - 16)];
    }
    __syncthreads();

    const float* w = sw + nl * NODE_SMEM;

    const int4 c0 = *(const int4*)(in_ixs + (size_t)node * 8);
    const int4 c1 = *(const int4*)(in_ixs + (size_t)node * 8 + 4);
    int cols[8] = {c0.x, c0.y, c0.z, c0.w, c1.x, c1.y, c1.z, c1.w};

    // Gather: 8 columns, each 256B contiguous per warp; 8B (one lane pair) per thread.
    // src buffer is dead after this layer -> streaming load (evict-first).
    u64 g[8];
#pragma unroll
    for (int d = 0; d < 8; d++)
        g[d] = ldg_cs64(src + (((size_t)cols[d]) << 6) + (lane << 1));

    // Output accumulators (8 out dims x 2 batches), init with b2.
    u64 o[8];
#pragma unroll
    for (int d = 0; d < 8; d++) {
        float bd = w[272 + d];
        o[d] = pack2(bd, bd);
    }

    // For each hidden unit j: h_j = elu(sum_d g_d * W1[j][d] + b1[j]),
    // then o_d += h_j * W2[d][j].
#pragma unroll
    for (int j = 0; j < 16; j++) {
        float bj = w[256 + j];
        u64 a = pack2(bj, bj);
#pragma unroll
        for (int d = 0; d < 8; d++) {
            float wv = w[j * 8 + d];
            fma2(a, g[d], pack2(wv, wv), a);
        }
        float h0, h1;
        unpack2(a, h0, h1);
        h0 = elu1(h0); h1 = elu1(h1);
        const u64 hh = pack2(h0, h1);
#pragma unroll
        for (int d = 0; d < 8; d++) {
            float wv = w[128 + d * 16 + j];
            fma2(o[d], hh, pack2(wv, wv), o[d]);
        }
    }

    // Residual (f32x2 add) + store; output columns [8*node, 8*node+8) contiguous.
#pragma unroll
    for (int d = 0; d < 8; d++) {
        const size_t col = (size_t)node * 8 + d;
        const u64 r = *(const u64*)(x0T + (col << 6) + (lane << 1));
        *(u64*)(dst + (col << 6) + (lane << 1)) = add2(o[d], r);
    }
}

extern "C" void kernel_launch(void* const* d_in, const int* in_sizes, int n_in,
                              void* d_out, int out_size) {
    const float* x0     = (const float*)d_in[0];
    const float* W1     = (const float*)d_in[1];
    const float* b1     = (const float*)d_in[2];
    const float* W2     = (const float*)d_in[3];
    const float* b2     = (const float*)d_in[4];
    const int*   in_ixs = (const int*)d_in[5];
    float* out = (float*)d_out;

    float *x0T, *xA, *xB;
    cudaGetSymbolAddress((void**)&x0T, g_x0T);
    cudaGetSymbolAddress((void**)&xA,  g_xA);
    cudaGetSymbolAddress((void**)&xB,  g_xB);

    dim3 tb(32, 32);
    k_transpose_in<<<dim3(E / 32, B / 32), tb>>>(x0, x0T);

    const float* src = x0T;
    float* bufs[2] = {xA, xB};
    for (int L = 0; L < LAYERS; L++) {
        float* dst = bufs[L & 1];
        layer_kernel<<<F_NODES / NPB, NPB * 32>>>(src, dst, W1, b1, W2, b2, in_ixs, x0T);
        src = dst;
    }
    k_transpose_out<<<dim3(E / 32, B / 32), tb>>>(src, out);
}